// round 1
// baseline (speedup 1.0000x reference)
#include <cuda_runtime.h>

// uDTW forward DP. B=32, N=M=512, GAMMA=1 (alpha=1), BANDWIDTH=0, BIG=1e30.
// One CTA per batch; thread t owns row i=t+1; anti-diagonal wavefront with
// 3-deep cyclic smem ring buffers for (R, SigR, D, Sig) diagonals.
// One __syncthreads per diagonal; global loads prefetched 2 diagonals ahead.

#define BIGV 1e30f
#define NN 512
#define MM 512
#define BB 32

__global__ __launch_bounds__(512, 1)
void softdtw_udtw_kernel(const float* __restrict__ D,
                         const float* __restrict__ Sig,
                         float* __restrict__ out) {
    __shared__ float sR[3][NN + 1];   // R diagonals
    __shared__ float sS[3][NN + 1];   // SigR diagonals
    __shared__ float sD[3][NN + 1];   // D diagonal values (Dp[i][j])
    __shared__ float sG[3][NN + 1];   // Sig diagonal values

    const int b = blockIdx.x;
    const int t = threadIdx.x;               // row i = t + 1
    const float* pD = D + (size_t)b * NN * MM + (size_t)t * MM;
    const float* pG = Sig + (size_t)b * NN * MM + (size_t)t * MM;

    // ---- init ring buffers: R/S = BIG, D/G = 0; then R[0][0]=S[0][0]=0 ----
    for (int idx = t; idx < 3 * (NN + 1); idx += 512) {
        int bi = idx / (NN + 1), ii = idx - bi * (NN + 1);
        sR[bi][ii] = BIGV; sS[bi][ii] = BIGV;
        sD[bi][ii] = 0.0f; sG[bi][ii] = 0.0f;
    }
    __syncthreads();
    if (t == 0) { sR[0][0] = 0.0f; sS[0][0] = 0.0f; }
    __syncthreads();

    // Thread t is valid on diagonals d in [t+2, t+513] (j = d - i in [1, M]).
    const int dlo = t + 2;
    const int dhi = t + 513;

    // ---- prefetch D/Sig for d=2 and d=3 (col = d - t - 2) ----
    float dv0 = 0.0f, gv0 = 0.0f, dv1 = 0.0f, gv1 = 0.0f;
    {
        int c = 0 - t;                        // d = 2
        if (c >= 0 && c < MM) { dv0 = pD[c]; gv0 = pG[c]; }
        c = 1 - t;                            // d = 3
        if (c >= 0 && c < MM) { dv1 = pD[c]; gv1 = pG[c]; }
    }

    float lastR = BIGV, lastS = BIGV;
    int cur = 2, pm1 = 1, pm2 = 0;           // buffers for diag d, d-1, d-2

    #pragma unroll 1
    for (int d = 2; d <= NN + MM; ++d) {
        const bool valid = (d >= dlo) && (d <= dhi);
        const float Dd = dv0, Gd = gv0;

        if (valid) {
            // softmax weights from R neighbors (alpha = 1)
            float rr0 = -sR[pm2][t];          // R[i-1][j-1]
            float rr1 = -sR[pm1][t];          // R[i-1][j]
            float rr2 = -sR[pm1][t + 1];      // R[i][j-1]
            float rmax = fmaxf(fmaxf(rr0, rr1), rr2);
            float e0 = __expf(rr0 - rmax);
            float e1 = __expf(rr1 - rmax);
            float e2 = __expf(rr2 - rmax);
            float inv = 1.0f / (e0 + e1 + e2);
            float w0 = e0 * inv, w1 = e1 * inv, w2 = e2 * inv;

            float nR = Dd + w0 * sD[pm2][t] + w1 * sD[pm1][t] + w2 * sD[pm1][t + 1];
            float nS = Gd + w0 * sG[pm2][t] + w1 * sG[pm1][t] + w2 * sG[pm1][t + 1];

            sR[cur][t + 1] = nR;  sS[cur][t + 1] = nS;
            sD[cur][t + 1] = Dd;  sG[cur][t + 1] = Gd;
            lastR = nR; lastS = nS;
        }
        if (t == 0) { sR[cur][0] = BIGV; sS[cur][0] = BIGV; }

        // rotate prefetch registers; issue loads for diagonal d+2
        dv0 = dv1; gv0 = gv1;
        {
            int c = d - t;                    // (d+2) - t - 2
            if (c >= 0 && c < MM) { dv1 = pD[c]; gv1 = pG[c]; }
            else                  { dv1 = 0.0f; gv1 = 0.0f; }
        }

        // rotate ring: next step's d-2 becomes current pm1, etc.
        int tmp = pm2; pm2 = pm1; pm1 = cur; cur = tmp;
        __syncthreads();
    }

    // final cell (N, M) lives in thread t = NN-1 at diagonal d = N+M
    if (t == NN - 1) {
        out[b] = lastR;          // R[:, N, M]
        out[BB + b] = lastS;     // SigR[:, N, M]
    }
}

extern "C" void kernel_launch(void* const* d_in, const int* in_sizes, int n_in,
                              void* d_out, int out_size) {
    const float* D   = (const float*)d_in[0];
    const float* Sig = (const float*)d_in[1];
    float* out = (float*)d_out;
    softdtw_udtw_kernel<<<BB, 512>>>(D, Sig, out);
}

// round 2
// speedup vs baseline: 1.2220x; 1.2220x over previous
#include <cuda_runtime.h>

// uDTW forward DP. B=32, N=M=512, alpha=1, BANDWIDTH=0, BIG=1e30.
// 1 CTA per batch, 256 threads, 2 rows per thread (rows 2t+1, 2t+2, 1-indexed).
// Cross-row dependency is only "row below -> row above": adjacent-lane shfl_up
// inside a warp, parity-double-buffered smem slots across the 7 warp boundaries.
// S (SigR) never feeds the recurrence -> only thread 255 tracks it for output.

#define BIGV 1e30f
#define NN 512
#define BB 32

__global__ __launch_bounds__(256, 1)
void softdtw_udtw_k2(const float* __restrict__ D,
                     const float* __restrict__ Sig,
                     float* __restrict__ out) {
    __shared__ float bR[2][8];   // [parity][warp] boundary R (lane31's row-b)
    __shared__ float bD[2][8];   // [parity][warp] boundary D

    const int b    = blockIdx.x;
    const int t    = threadIdx.x;
    const int lane = t & 31;
    const int w    = t >> 5;
    const int i0   = 2 * t + 1;          // first (upper) row, 1-indexed
    const int i1   = i0 + 1;             // second (lower) row
    const bool lastT = (t == 255);

    const float* rowD0 = D   + (size_t)b * NN * NN + (size_t)(i0 - 1) * NN;
    const float* rowD1 = rowD0 + NN;
    const float* rowG0 = Sig + (size_t)b * NN * NN + (size_t)(i0 - 1) * NN;
    const float* rowG1 = rowG0 + NN;

    if (t < 16) { bR[t >> 3][t & 7] = BIGV; bD[t >> 3][t & 7] = 0.f; }

    // Per-row DP state: R at diag d-1/d-2, D value at diag d-1/d-2.
    float R1a = BIGV, R2a = BIGV, D1a = 0.f, D2a = 0.f;   // row i0
    float R1b = BIGV, R2b = BIGV, D1b = 0.f;              // row i1
    float G1a = 0.f, G2a = 0.f, G1b = 0.f;                // Sig state (thread 255)
    // Held predecessor-row (i0-1) values at diag d-2:
    float pR2 = (t == 0) ? 0.f : BIGV;
    float pD2 = 0.f;

    // Prefetch pipeline: value for step d (cur) and d+1 (next).
    // col(d, i) = d - i - 1 (0-based data column of D[i][d-i]).
    float da0, da1, db0, db1;
    float ga0 = 0.f, ga1 = 0.f, gb0 = 0.f, gb1 = 0.f;
    {
        int c;
        c = 2 - i0 - 1; da0 = ((unsigned)c < NN) ? rowD0[c] : 0.f;
        c = 3 - i0 - 1; da1 = ((unsigned)c < NN) ? rowD0[c] : 0.f;
        c = 2 - i1 - 1; db0 = ((unsigned)c < NN) ? rowD1[c] : 0.f;
        c = 3 - i1 - 1; db1 = ((unsigned)c < NN) ? rowD1[c] : 0.f;
        // G columns at d=2,3 are negative for t==255 -> stay 0
    }
    __syncthreads();

    float lastS = BIGV;

    #pragma unroll 2
    for (int d = 2; d <= 2 * NN; ++d) {
        // Predecessor-row values at diag d-1 (neighbor thread's row-b state).
        float pR1 = __shfl_up_sync(0xffffffffu, R1b, 1);
        float pD1 = __shfl_up_sync(0xffffffffu, D1b, 1);
        if (lane == 0) {
            if (w == 0) { pR1 = BIGV; pD1 = 0.f; }       // virtual row 0
            else { pR1 = bR[(d - 1) & 1][w - 1]; pD1 = bD[(d - 1) & 1][w - 1]; }
        }

        const bool v0 = (d >= i0 + 1) && (d <= i0 + NN);
        const bool v1 = (d >= i1 + 1) && (d <= i1 + NN);

        // ---- cell (i0, d-i0): preds R = (pR2, pR1, R1a), D = (pD2, pD1, D1a)
        float nR0;
        {
            float rmin = fminf(fminf(pR2, pR1), R1a);    // rmax of -R = -rmin
            float e0 = __expf(rmin - pR2);
            float e1 = __expf(rmin - pR1);
            float e2 = __expf(rmin - R1a);
            float inv = __fdividef(1.f, e0 + e1 + e2);
            nR0 = fmaf(inv, fmaf(e2, D1a, fmaf(e1, pD1, e0 * pD2)), da0);
        }
        // ---- cell (i1, d-i1): preds R = (R2a, R1a, R1b), D = (D2a, D1a, D1b)
        float nR1, e0b, e1b, e2b, invb;
        {
            float rmin = fminf(fminf(R2a, R1a), R1b);
            e0b = __expf(rmin - R2a);
            e1b = __expf(rmin - R1a);
            e2b = __expf(rmin - R1b);
            invb = __fdividef(1.f, e0b + e1b + e2b);
            nR1 = fmaf(invb, fmaf(e2b, D1b, fmaf(e1b, D1a, e0b * D2a)), db0);
        }
        if (lastT) {
            // SigR for row i1 — same weights, Sig values. Final value at d=1024.
            float nS1 = fmaf(invb, fmaf(e2b, G1b, fmaf(e1b, G1a, e0b * G2a)), gb0);
            if (v1) lastS = nS1;
        }

        // ---- rotate state to "end of step d"
        pR2 = pR1; pD2 = pD1;
        R2a = R1a; R1a = v0 ? nR0 : BIGV;
        D2a = D1a; D1a = da0;                // da0 already 0 outside range
        R2b = R1b; R1b = v1 ? nR1 : BIGV;
        D1b = db0;
        G2a = G1a; G1a = ga0; G1b = gb0;

        // publish boundary (post-rotation = diag d values of row i1)
        if (lane == 31) { bR[d & 1][w] = R1b; bD[d & 1][w] = D1b; }

        // advance prefetch: issue loads for step d+2 (col = d + 1 - i)
        da0 = da1; db0 = db1; ga0 = ga1; gb0 = gb1;
        {
            int c0 = d + 1 - i0, c1 = d + 1 - i1;
            da1 = ((unsigned)c0 < NN) ? rowD0[c0] : 0.f;
            db1 = ((unsigned)c1 < NN) ? rowD1[c1] : 0.f;
            if (lastT) {
                ga1 = ((unsigned)c0 < NN) ? rowG0[c0] : 0.f;
                gb1 = ((unsigned)c1 < NN) ? rowG1[c1] : 0.f;
            }
        }
        __syncthreads();
    }

    if (lastT) {
        out[b]      = R1b;    // R[b, N, M]
        out[BB + b] = lastS;  // SigR[b, N, M]
    }
}

extern "C" void kernel_launch(void* const* d_in, const int* in_sizes, int n_in,
                              void* d_out, int out_size) {
    const float* D   = (const float*)d_in[0];
    const float* Sig = (const float*)d_in[1];
    float* out = (float*)d_out;
    softdtw_udtw_k2<<<BB, 256>>>(D, Sig, out);
}